// round 2
// baseline (speedup 1.0000x reference)
#include <cuda_runtime.h>
#include <cuda_bf16.h>

// Problem constants (fixed shapes for this problem instance)
#define N_C 500000
#define N_F 2000000
#define KNBR 8
#define ROWW (KNBR + 2)   // 8 neighbor cols + pad + count

// Scratch: d = input - pred, padded to float4 for 16B-aligned single-sector gathers.
__device__ float4 g_d[N_C + N_F];
__device__ double g_acc;

// ---------------------------------------------------------------------------
// Kernel 1: compute d = input - pred for both meshes; thread 0 zeroes the
// accumulator (safe: stream order puts this kernel fully before the loss
// kernels).
// ---------------------------------------------------------------------------
__global__ void diff_kernel(const float* __restrict__ ci,
                            const float* __restrict__ cp,
                            const float* __restrict__ fi,
                            const float* __restrict__ fp) {
    int i = blockIdx.x * blockDim.x + threadIdx.x;
    if (i == 0) g_acc = 0.0;
    const int total = N_C + N_F;
    if (i >= total) return;

    const float* __restrict__ a;
    const float* __restrict__ b;
    int j;
    if (i < N_C) { a = ci; b = cp; j = i; }
    else         { a = fi; b = fp; j = i - N_C; }

    const int base = 3 * j;
    float4 d;
    d.x = a[base + 0] - b[base + 0];
    d.y = a[base + 1] - b[base + 1];
    d.z = a[base + 2] - b[base + 2];
    d.w = 0.0f;
    g_d[i] = d;
}

// ---------------------------------------------------------------------------
// Kernel 2: per-vertex Laplacian-difference squared norm + block reduction.
//   diff = d[i] - (sum_j d[idx[j]]) / count
//   partial += ||diff||^2 ; block sum -> atomicAdd(double) scaled by 0.5/n
// ---------------------------------------------------------------------------
__global__ void loss_kernel(const int* __restrict__ lap, int n, int base,
                            double scale) {
    const int i = blockIdx.x * blockDim.x + threadIdx.x;
    float v = 0.0f;
    if (i < n) {
        const float4* __restrict__ d = g_d + base;
        const float4 di = d[i];
        const int* __restrict__ row = lap + (size_t)i * ROWW;

        int idx[KNBR];
#pragma unroll
        for (int j = 0; j < KNBR; j++) idx[j] = row[j];
        const int cnt = row[KNBR + 1];

        float sx = 0.0f, sy = 0.0f, sz = 0.0f;
#pragma unroll
        for (int j = 0; j < KNBR; j++) {
            const int id = idx[j];
            if (id >= 0) {
                const float4 nv = d[id];
                sx += nv.x; sy += nv.y; sz += nv.z;
            }
        }
        const float inv = 1.0f / (float)cnt;
        const float ex = di.x - sx * inv;
        const float ey = di.y - sy * inv;
        const float ez = di.z - sz * inv;
        v = ex * ex + ey * ey + ez * ez;
    }

    // warp reduce
#pragma unroll
    for (int off = 16; off > 0; off >>= 1)
        v += __shfl_down_sync(0xFFFFFFFFu, v, off);

    __shared__ float warp_sums[8];  // 256 threads / 32
    const int lane = threadIdx.x & 31;
    const int wid  = threadIdx.x >> 5;
    if (lane == 0) warp_sums[wid] = v;
    __syncthreads();

    if (wid == 0) {
        float s = (lane < (blockDim.x >> 5)) ? warp_sums[lane] : 0.0f;
#pragma unroll
        for (int off = 4; off > 0; off >>= 1)
            s += __shfl_down_sync(0xFFFFFFFFu, s, off);
        if (lane == 0)
            atomicAdd(&g_acc, (double)s * scale);
    }
}

// ---------------------------------------------------------------------------
// Kernel 3: write result
// ---------------------------------------------------------------------------
__global__ void finalize_kernel(float* __restrict__ out) {
    out[0] = (float)g_acc;
}

extern "C" void kernel_launch(void* const* d_in, const int* in_sizes, int n_in,
                              void* d_out, int out_size) {
    const float* ci = (const float*)d_in[0];  // coarse_input  (N_C,3)
    const float* cp = (const float*)d_in[1];  // coarse_pred   (N_C,3)
    const float* fi = (const float*)d_in[2];  // fine_input    (N_F,3)
    const float* fp = (const float*)d_in[3];  // fine_pred     (N_F,3)
    const int* lic  = (const int*)d_in[4];    // lap_idx_coarse (N_C,10)
    const int* lif  = (const int*)d_in[5];    // lap_idx_fine   (N_F,10)

    const int nc = in_sizes[0] / 3;
    const int nf = in_sizes[2] / 3;

    const int T = 256;
    const int total = nc + nf;

    diff_kernel<<<(total + T - 1) / T, T>>>(ci, cp, fi, fp);
    loss_kernel<<<(nc + T - 1) / T, T>>>(lic, nc, 0,  0.5 / (double)nc);
    loss_kernel<<<(nf + T - 1) / T, T>>>(lif, nf, nc, 0.5 / (double)nf);
    finalize_kernel<<<1, 1>>>((float*)d_out);
}